// round 9
// baseline (speedup 1.0000x reference)
#include <cuda_runtime.h>
#include <cuda_bf16.h>
#include <cstdint>

#define SEQ   512
#define BATCH 256
#define HID   128
#define MROWS (SEQ * BATCH)        /* 131072 */
#define KIN   300
#define KPAD  320                  /* 5 chunks of 64 */
#define ALPHA 0.1f

typedef unsigned long long u64;

/* ---------------- packed f32x2 helpers ----------------------------- */
__device__ __forceinline__ u64 pack2(float lo, float hi) {
    u64 r; asm("mov.b64 %0, {%1, %2};" : "=l"(r) : "f"(lo), "f"(hi)); return r;
}
__device__ __forceinline__ float2 unpack2(u64 v) {
    float2 f; asm("mov.b64 {%0, %1}, %2;" : "=f"(f.x), "=f"(f.y) : "l"(v)); return f;
}
__device__ __forceinline__ void fma2(u64 &acc, u64 a, u64 b) {
    asm("fma.rn.f32x2 %0, %1, %2, %0;" : "+l"(acc) : "l"(a), "l"(b));
}

/* ---------------- warp-MMA helpers (sm_80+ baseline PTX) ----------- */
__device__ __forceinline__ uint32_t smem_u32(const void* p) {
    uint32_t a;
    asm("{ .reg .u64 t; cvta.to.shared.u64 t, %1; cvt.u32.u64 %0, t; }" : "=r"(a) : "l"(p));
    return a;
}
#define SW128(off) ((off) ^ (((off) >> 3) & 0x70))

__device__ __forceinline__ void ldsm4(uint32_t &r0, uint32_t &r1, uint32_t &r2, uint32_t &r3,
                                      uint32_t addr) {
    asm volatile("ldmatrix.sync.aligned.m8n8.x4.shared.b16 {%0,%1,%2,%3}, [%4];"
                 : "=r"(r0), "=r"(r1), "=r"(r2), "=r"(r3) : "r"(addr));
}
__device__ __forceinline__ void mma16816(float* d, const uint32_t* a, const uint32_t* b) {
    asm volatile("mma.sync.aligned.m16n8k16.row.col.f32.bf16.bf16.f32 "
                 "{%0,%1,%2,%3}, {%4,%5,%6,%7}, {%8,%9}, {%0,%1,%2,%3};"
                 : "+f"(d[0]), "+f"(d[1]), "+f"(d[2]), "+f"(d[3])
                 : "r"(a[0]), "r"(a[1]), "r"(a[2]), "r"(a[3]), "r"(b[0]), "r"(b[1]));
}

/* cp.async 16B (LDGSTS) */
#define CP_A16(dst, src) \
    asm volatile("cp.async.ca.shared.global [%0], [%1], 16;" :: "r"(dst), "l"(src) : "memory")
#define CP_COMMIT() asm volatile("cp.async.commit_group;" ::: "memory")
#define CP_WAIT0()  asm volatile("cp.async.wait_group 0;" ::: "memory")

/* split one float4 into packed bf16x2 hi / lo words */
__device__ __forceinline__ void split4(float4 v, uint32_t &hp0, uint32_t &hp1,
                                       uint32_t &lp0, uint32_t &lp1) {
    const __nv_bfloat16 h0 = __float2bfloat16_rn(v.x);
    const __nv_bfloat16 h1 = __float2bfloat16_rn(v.y);
    const __nv_bfloat16 h2 = __float2bfloat16_rn(v.z);
    const __nv_bfloat16 h3 = __float2bfloat16_rn(v.w);
    __nv_bfloat162 t0 = __halves2bfloat162(h0, h1);
    __nv_bfloat162 t1 = __halves2bfloat162(h2, h3);
    hp0 = *(uint32_t*)&t0; hp1 = *(uint32_t*)&t1;
    __nv_bfloat162 u0 = __halves2bfloat162(__float2bfloat16_rn(v.x - __bfloat162float(h0)),
                                           __float2bfloat16_rn(v.y - __bfloat162float(h1)));
    __nv_bfloat162 u1 = __halves2bfloat162(__float2bfloat16_rn(v.z - __bfloat162float(h2)),
                                           __float2bfloat16_rn(v.w - __bfloat162float(h3)));
    lp0 = *(uint32_t*)&u0; lp1 = *(uint32_t*)&u1;
}

#define STS128(addr, a, b, c_, d_) \
    asm volatile("st.shared.v4.b32 [%0], {%1,%2,%3,%4};" :: "r"(addr), \
                 "r"(a), "r"(b), "r"(c_), "r"(d_) : "memory")

/* ---------------- scratch ------------------------------------------ */
__device__ float g_xp[MROWS * HID];
__device__ float g_hs[MROWS * HID];
__device__ __nv_bfloat16 g_Wbh[HID * KPAD];   /* W_ih hi  [n][k] */
__device__ __nv_bfloat16 g_Wbl[HID * KPAD];   /* W_ih lo  [n][k] */
__device__ __nv_bfloat16 g_W1h[64 * HID];     /* W1 hi    [n][k] */
__device__ __nv_bfloat16 g_W1l[64 * HID];     /* W1 lo    [n][k] */
__device__ float g_bias[HID];

/* ------------------------------------------------------------------ */
__global__ void prep_kernel(const float* __restrict__ W_ih,
                            const float* __restrict__ W1,
                            const float* __restrict__ b_ih,
                            const float* __restrict__ b_hh)
{
    const int i = blockIdx.x * 256 + threadIdx.x;
    if (i < HID * KPAD) {
        const int n = i / KPAD, k = i % KPAD;
        const float w = (k < KIN) ? W_ih[n * KIN + k] : 0.f;
        const __nv_bfloat16 h = __float2bfloat16_rn(w);
        g_Wbh[i] = h;
        g_Wbl[i] = __float2bfloat16_rn(w - __bfloat162float(h));
    }
    if (i < 64 * HID) {
        const float w = W1[i];
        const __nv_bfloat16 h = __float2bfloat16_rn(w);
        g_W1h[i] = h;
        g_W1l[i] = __float2bfloat16_rn(w - __bfloat162float(h));
    }
    if (i < HID) g_bias[i] = b_ih[i] + b_hh[i];
}

/* ------------------------------------------------------------------ */
/* proj: xp[M][128] = x[M][300] @ W_ih^T via warp-MMA bf16 3-product  */
/* ------------------------------------------------------------------ */
#define PROJ_SMEM (4 * 16384)

__global__ __launch_bounds__(256)
void proj_mma_kernel(const float* __restrict__ x,
                     const __nv_bfloat16* __restrict__ Wbh,
                     const __nv_bfloat16* __restrict__ Wbl,
                     const float* __restrict__ bias, float* __restrict__ C)
{
    extern __shared__ __align__(1024) char sm[];
    const uint32_t base = smem_u32(sm);
    const uint32_t A_H = base, A_L = base + 16384;
    const uint32_t B_H = base + 32768, B_L = base + 49152;

    const int tid  = threadIdx.x;
    const int lane = tid & 31;
    const int wid  = tid >> 5;
    const int wm   = wid & 3;
    const int wn   = wid >> 2;
    const int blockM = blockIdx.x * 128;

    float d[2][8][4];
#pragma unroll
    for (int mi = 0; mi < 2; mi++)
#pragma unroll
        for (int ni = 0; ni < 8; ni++)
#pragma unroll
            for (int q = 0; q < 4; q++) d[mi][ni][q] = 0.f;

    const int srow  = tid >> 1;
    const int shalf = (tid & 1) * 32;
    const float* xrow = x + (long)(blockM + srow) * KIN;
    const uint32_t arow = srow * 128 + shalf * 2;

    const int rowA = (lane & 7) + ((lane >> 3) & 1) * 8;
    const int kxA  = (lane >> 4) * 16;
    const int rowB = (lane & 7) + (lane >> 4) * 8;
    const int kxB  = ((lane >> 3) & 1) * 16;

    for (int c = 0; c < 5; ++c) {
        {
            const __nv_bfloat16* bhp = Wbh + srow * KPAD + c * 64 + shalf;
            const __nv_bfloat16* blp = Wbl + srow * KPAD + c * 64 + shalf;
#pragma unroll
            for (int i = 0; i < 4; i++) {
                const uint32_t off = SW128(arow + i * 16);
                CP_A16(B_H + off, bhp + i * 8);
                CP_A16(B_L + off, blp + i * 8);
            }
            CP_COMMIT();
        }

#pragma unroll
        for (int i = 0; i < 8; i += 2) {
            uint32_t h0, h1, h2, h3, l0, l1, l2, l3;
            {
                const int gcol = c * 64 + shalf + i * 4;
                float4 v = make_float4(0.f, 0.f, 0.f, 0.f);
                if (gcol < KIN) v = *(const float4*)(xrow + gcol);
                split4(v, h0, h1, l0, l1);
            }
            {
                const int gcol = c * 64 + shalf + (i + 1) * 4;
                float4 v = make_float4(0.f, 0.f, 0.f, 0.f);
                if (gcol < KIN) v = *(const float4*)(xrow + gcol);
                split4(v, h2, h3, l2, l3);
            }
            const uint32_t off = SW128(arow + i * 8);
            STS128(A_H + off, h0, h1, h2, h3);
            STS128(A_L + off, l0, l1, l2, l3);
        }
        CP_WAIT0();
        __syncthreads();

#pragma unroll
        for (int ks = 0; ks < 4; ++ks) {
            uint32_t ah[2][4], al[2][4];
#pragma unroll
            for (int mi = 0; mi < 2; mi++) {
                const uint32_t off = SW128((uint32_t)((wm * 32 + mi * 16 + rowA) * 128
                                                      + ks * 32 + kxA));
                ldsm4(ah[mi][0], ah[mi][1], ah[mi][2], ah[mi][3], A_H + off);
                ldsm4(al[mi][0], al[mi][1], al[mi][2], al[mi][3], A_L + off);
            }
            uint32_t bh[8][2], bl[8][2];
#pragma unroll
            for (int nb = 0; nb < 4; nb++) {
                const uint32_t off = SW128((uint32_t)((wn * 64 + nb * 16 + rowB) * 128
                                                      + ks * 32 + kxB));
                uint32_t t0, t1, t2, t3;
                ldsm4(t0, t1, t2, t3, B_H + off);
                bh[2 * nb][0] = t0; bh[2 * nb][1] = t1;
                bh[2 * nb + 1][0] = t2; bh[2 * nb + 1][1] = t3;
                ldsm4(t0, t1, t2, t3, B_L + off);
                bl[2 * nb][0] = t0; bl[2 * nb][1] = t1;
                bl[2 * nb + 1][0] = t2; bl[2 * nb + 1][1] = t3;
            }
#pragma unroll
            for (int mi = 0; mi < 2; mi++)
#pragma unroll
                for (int ni = 0; ni < 8; ni++) {
                    mma16816(d[mi][ni], ah[mi], bh[ni]);
                    mma16816(d[mi][ni], ah[mi], bl[ni]);
                    mma16816(d[mi][ni], al[mi], bh[ni]);
                }
        }
        __syncthreads();
    }

    const int drow = lane >> 2;
    const int dcol = (lane & 3) * 2;
#pragma unroll
    for (int mi = 0; mi < 2; mi++) {
        const int m0 = blockM + wm * 32 + mi * 16 + drow;
#pragma unroll
        for (int ni = 0; ni < 8; ni++) {
            const int n = wn * 64 + ni * 8 + dcol;
            const float b0 = bias[n], b1 = bias[n + 1];
            *(float2*)(C + (long)m0 * HID + n) =
                make_float2(d[mi][ni][0] + b0, d[mi][ni][1] + b1);
            *(float2*)(C + (long)(m0 + 8) * HID + n) =
                make_float2(d[mi][ni][2] + b0, d[mi][ni][3] + b1);
        }
    }
}

/* ------------------------------------------------------------------ */
/* scan v8: 256 independent CTAs (1 batch each), 256 threads.         */
/* thread (j = tid>>1, sg = tid&1): k-half of 64 in regs (32 u64).    */
/* One shfl.xor(1); 8-warp barrier; 2 CTAs/SM hide each other's       */
/* per-step critical path. Depth-2 xp prefetch.                       */
/* ------------------------------------------------------------------ */
__global__ __launch_bounds__(256)
void scan_kernel(const float* __restrict__ xp, const float* __restrict__ Whh,
                 float* __restrict__ hs)
{
    const int tid = threadIdx.x;
    const int j   = tid >> 1;
    const int sg  = tid & 1;
    const int b   = blockIdx.x;

    __shared__ __align__(16) float hbuf[2][HID];

    u64 w[32];
    const u64* wp = (const u64*)(Whh + j * HID + sg * 64);
#pragma unroll
    for (int i = 0; i < 32; i++) w[i] = wp[i];

    if (tid < HID) hbuf[0][tid] = 0.f;

    const bool writer = (sg == 0);
    float xc0 = 0.f, xc1 = 0.f;
    if (writer) {
        xc0 = xp[((long)0 * BATCH + b) * HID + j];
        xc1 = xp[((long)1 * BATCH + b) * HID + j];
    }
    __syncthreads();

    int pp = 0;
    for (int t = 0; t < SEQ; ++t) {
        const float xcur = (t & 1) ? xc1 : xc0;
        if (writer && t + 2 < SEQ) {
            const float xn = xp[((long)(t + 2) * BATCH + b) * HID + j];
            if (t & 1) xc1 = xn; else xc0 = xn;
        }

        u64 a0 = 0ull, a1 = 0ull, a2 = 0ull, a3 = 0ull;
        const ulonglong2* hp = (const ulonglong2*)&hbuf[pp][sg * 64];
#pragma unroll
        for (int i = 0; i < 8; i++) {
            const ulonglong2 h0 = hp[2 * i];
            const ulonglong2 h1 = hp[2 * i + 1];
            fma2(a0, w[4 * i + 0], h0.x);
            fma2(a1, w[4 * i + 1], h0.y);
            fma2(a2, w[4 * i + 2], h1.x);
            fma2(a3, w[4 * i + 3], h1.y);
        }
        const float2 f0 = unpack2(a0), f1 = unpack2(a1);
        const float2 f2 = unpack2(a2), f3 = unpack2(a3);
        float s = ((f0.x + f1.x) + (f0.y + f1.y)) + ((f2.x + f3.x) + (f2.y + f3.y));
        s += __shfl_xor_sync(0xffffffffu, s, 1);

        if (writer) {
            const float v = xcur + s;
            const float e = __expf(v + v);
            const float h = 1.f - __fdividef(2.f, e + 1.f);
            hbuf[pp ^ 1][j] = h;
            hs[((long)t * BATCH + b) * HID + j] = h;
        }
        pp ^= 1;
        __syncthreads();
    }
}

/* ------------------------------------------------------------------ */
/* Fused MLP v8: smem overlay — y1 + tail weights reuse the staging   */
/* region after the GEMM; smem 92KB -> 48KB -> 4 CTAs/SM.             */
/* ------------------------------------------------------------------ */
#define MLP_A_H   0
#define MLP_A_L   16384
#define MLP_B_H   32768
#define MLP_B_L   40960
#define MLP_Y1    0                             /* overlays A_H/A_L/B_H */
#define MLP_TW    34048                         /* after y1 (33792)      */
#define MLP_SMEM  49152

__global__ __launch_bounds__(256)
void mlp_kernel(const float* __restrict__ A,
                const __nv_bfloat16* __restrict__ W1h,
                const __nv_bfloat16* __restrict__ W1l,
                const float* __restrict__ b1,
                const float* __restrict__ W2, const float* __restrict__ b2,
                const float* __restrict__ W3, const float* __restrict__ b3,
                const float* __restrict__ W4, const float* __restrict__ b4,
                const float* __restrict__ W5, const float* __restrict__ b5,
                float* __restrict__ out)
{
    extern __shared__ __align__(1024) char sm[];
    const uint32_t base = smem_u32(sm);
    const uint32_t A_H = base + MLP_A_H, A_L = base + MLP_A_L;
    const uint32_t B_H = base + MLP_B_H, B_L = base + MLP_B_L;
    float* const y1s = (float*)(sm + MLP_Y1);    /* [128][66], post-GEMM */
    float* const sW2 = (float*)(sm + MLP_TW);    /* 2048 */
    float* const sW3 = sW2 + 2048;               /* 512  */
    float* const sW4 = sW3 + 512;                /* 128  */
    float* const sW5 = sW4 + 128;                /* 8    */
    float* const sb2 = sW5 + 8;                  /* 32   */
    float* const sb3 = sb2 + 32;                 /* 16   */
    float* const sb4 = sb3 + 16;                 /* 8    */
    float* const sb5 = sb4 + 8;                  /* 1    */

    const int tid  = threadIdx.x;
    const int lane = tid & 31;
    const int wid  = tid >> 5;
    const int wm   = wid & 3;
    const int wn   = wid >> 2;
    const int blockM = blockIdx.x * 128;

    float d[2][4][4];
#pragma unroll
    for (int mi = 0; mi < 2; mi++)
#pragma unroll
        for (int ni = 0; ni < 4; ni++)
#pragma unroll
            for (int q = 0; q < 4; q++) d[mi][ni][q] = 0.f;

    const int srow  = tid >> 1;
    const int shalf = (tid & 1) * 32;
    const float* Arow = A + (long)(blockM + srow) * HID;
    const uint32_t arow = srow * 128 + shalf * 2;

    const int bn  = tid & 63;
    const int bsg = tid >> 6;

    const int rowA = (lane & 7) + ((lane >> 3) & 1) * 8;
    const int kxA  = (lane >> 4) * 16;
    const int rowB = (lane & 7) + (lane >> 4) * 8;
    const int kxB  = ((lane >> 3) & 1) * 16;

    for (int c = 0; c < 2; ++c) {
        {
            const __nv_bfloat16* bhp = W1h + bn * HID + c * 64 + bsg * 16;
            const __nv_bfloat16* blp = W1l + bn * HID + c * 64 + bsg * 16;
            const uint32_t o0 = SW128((uint32_t)(bn * 128 + bsg * 32));
            const uint32_t o1 = SW128((uint32_t)(bn * 128 + bsg * 32 + 16));
            CP_A16(B_H + o0, bhp);
            CP_A16(B_H + o1, bhp + 8);
            CP_A16(B_L + o0, blp);
            CP_A16(B_L + o1, blp + 8);
            CP_COMMIT();
        }
#pragma unroll
        for (int i = 0; i < 8; i += 2) {
            uint32_t h0, h1, h2, h3, l0, l1, l2, l3;
            float4 v0 = *(const float4*)(Arow + c * 64 + shalf + i * 4);
            float4 v1 = *(const float4*)(Arow + c * 64 + shalf + (i + 1) * 4);
            split4(v0, h0, h1, l0, l1);
            split4(v1, h2, h3, l2, l3);
            const uint32_t off = SW128(arow + i * 8);
            STS128(A_H + off, h0, h1, h2, h3);
            STS128(A_L + off, l0, l1, l2, l3);
        }
        CP_WAIT0();
        __syncthreads();

#pragma unroll
        for (int ks = 0; ks < 4; ++ks) {
            uint32_t ah[2][4], al[2][4];
#pragma unroll
            for (int mi = 0; mi < 2; mi++) {
                const uint32_t off = SW128((uint32_t)((wm * 32 + mi * 16 + rowA) * 128
                                                      + ks * 32 + kxA));
                ldsm4(ah[mi][0], ah[mi][1], ah[mi][2], ah[mi][3], A_H + off);
                ldsm4(al[mi][0], al[mi][1], al[mi][2], al[mi][3], A_L + off);
            }
            uint32_t bh[4][2], bl[4][2];
#pragma unroll
            for (int nb = 0; nb < 2; nb++) {
                const uint32_t off = SW128((uint32_t)((wn * 32 + nb * 16 + rowB) * 128
                                                      + ks * 32 + kxB));
                uint32_t t0, t1, t2, t3;
                ldsm4(t0, t1, t2, t3, B_H + off);
                bh[2 * nb][0] = t0; bh[2 * nb][1] = t1;
                bh[2 * nb + 1][0] = t2; bh[2 * nb + 1][1] = t3;
                ldsm4(t0, t1, t2, t3, B_L + off);
                bl[2 * nb][0] = t0; bl[2 * nb][1] = t1;
                bl[2 * nb + 1][0] = t2; bl[2 * nb + 1][1] = t3;
            }
#pragma unroll
            for (int mi = 0; mi < 2; mi++)
#pragma unroll
                for (int ni = 0; ni < 4; ni++) {
                    mma16816(d[mi][ni], ah[mi], bh[ni]);
                    mma16816(d[mi][ni], ah[mi], bl[ni]);
                    mma16816(d[mi][ni], al[mi], bh[ni]);
                }
        }
        __syncthreads();
    }

    /* ---- phase 2: staging region is dead; overlay y1 + tail wts ---- */
    const int drow = lane >> 2;
    const int dcol = (lane & 3) * 2;
#pragma unroll
    for (int mi = 0; mi < 2; mi++) {
        const int m0 = wm * 32 + mi * 16 + drow;
#pragma unroll
        for (int ni = 0; ni < 4; ni++) {
            const int n = wn * 32 + ni * 8 + dcol;
            const float bb0 = b1[n], bb1 = b1[n + 1];
            float v0 = d[mi][ni][0] + bb0, v1 = d[mi][ni][1] + bb1;
            float v2 = d[mi][ni][2] + bb0, v3 = d[mi][ni][3] + bb1;
            v0 = v0 > 0.f ? v0 : ALPHA * v0;
            v1 = v1 > 0.f ? v1 : ALPHA * v1;
            v2 = v2 > 0.f ? v2 : ALPHA * v2;
            v3 = v3 > 0.f ? v3 : ALPHA * v3;
            *(float2*)&y1s[m0 * 66 + n]       = make_float2(v0, v1);
            *(float2*)&y1s[(m0 + 8) * 66 + n] = make_float2(v2, v3);
        }
    }
    for (int i = tid; i < 2048; i += 256) sW2[i] = W2[i];
    for (int i = tid; i < 512;  i += 256) sW3[i] = W3[i];
    if (tid < 128) sW4[tid] = W4[tid];
    if (tid < 32)  sb2[tid] = b2[tid];
    if (tid < 16)  sb3[tid] = b3[tid];
    if (tid < 8) { sb4[tid] = b4[tid]; sW5[tid] = W5[tid]; }
    if (tid == 0)  sb5[0] = b5[0];
    __syncthreads();

    /* tail: 2 threads per row (k-split), shfl.xor(1) reductions */
    const int row  = tid >> 1;
    const int half = tid & 1;

    u64 ap[16];
    const u64* yr = (const u64*)&y1s[row * 66 + half * 32];
#pragma unroll
    for (int i = 0; i < 16; i++) ap[i] = yr[i];

    const u64* w2p = (const u64*)sW2;
    const u64* w3p = (const u64*)sW3;
    const u64* w4p = (const u64*)sW4;
    const u64* w5p = (const u64*)sW5;

    float y2[32];
#pragma unroll
    for (int o = 0; o < 32; o++) {
        u64 a = 0ull;
        const ulonglong2* wv = (const ulonglong2*)&w2p[o * 32 + half * 16];
#pragma unroll
        for (int k = 0; k < 8; k++) {
            const ulonglong2 wk = wv[k];
            fma2(a, ap[2 * k],     wk.x);
            fma2(a, ap[2 * k + 1], wk.y);
        }
        const float2 f = unpack2(a);
        float s = f.x + f.y;
        s += __shfl_xor_sync(0xffffffffu, s, 1);
        s += sb2[o];
        y2[o] = s > 0.f ? s : ALPHA * s;
    }

    u64 a2[8];
#pragma unroll
    for (int i = 0; i < 8; i++) a2[i] = pack2(y2[half * 16 + 2 * i], y2[half * 16 + 2 * i + 1]);
    float y3[16];
#pragma unroll
    for (int o = 0; o < 16; o++) {
        u64 a = 0ull;
        const ulonglong2* wv = (const ulonglong2*)&w3p[o * 16 + half * 8];
#pragma unroll
        for (int k = 0; k < 4; k++) {
            const ulonglong2 wk = wv[k];
            fma2(a, a2[2 * k],     wk.x);
            fma2(a, a2[2 * k + 1], wk.y);
        }
        const float2 f = unpack2(a);
        float s = f.x + f.y;
        s += __shfl_xor_sync(0xffffffffu, s, 1);
        s += sb3[o];
        y3[o] = s > 0.f ? s : ALPHA * s;
    }

    u64 a3[4];
#pragma unroll
    for (int i = 0; i < 4; i++) a3[i] = pack2(y3[half * 8 + 2 * i], y3[half * 8 + 2 * i + 1]);
    float y4[8];
#pragma unroll
    for (int o = 0; o < 8; o++) {
        u64 a = 0ull;
        const ulonglong2* wv = (const ulonglong2*)&w4p[o * 8 + half * 4];
#pragma unroll
        for (int k = 0; k < 2; k++) {
            const ulonglong2 wk = wv[k];
            fma2(a, a3[2 * k],     wk.x);
            fma2(a, a3[2 * k + 1], wk.y);
        }
        const float2 f = unpack2(a);
        float s = f.x + f.y;
        s += __shfl_xor_sync(0xffffffffu, s, 1);
        s += sb4[o];
        y4[o] = s > 0.f ? s : ALPHA * s;
    }

    u64 a4[2];
#pragma unroll
    for (int i = 0; i < 2; i++) a4[i] = pack2(y4[half * 4 + 2 * i], y4[half * 4 + 2 * i + 1]);
    {
        u64 a = 0ull;
        const ulonglong2 wk = *(const ulonglong2*)&w5p[half * 2];
        fma2(a, a4[0], wk.x);
        fma2(a, a4[1], wk.y);
        const float2 f = unpack2(a);
        float s = f.x + f.y;
        s += __shfl_xor_sync(0xffffffffu, s, 1);
        s += sb5[0];
        s = s > 0.f ? s : ALPHA * s;
        if (half == 0) out[blockM + row] = s;
    }
}

/* ------------------------------------------------------------------ */
extern "C" void kernel_launch(void* const* d_in, const int* in_sizes, int n_in,
                              void* d_out, int out_size)
{
    const float* x    = (const float*)d_in[0];
    const float* W_ih = (const float*)d_in[1];
    const float* W_hh = (const float*)d_in[2];
    const float* b_ih = (const float*)d_in[3];
    const float* b_hh = (const float*)d_in[4];
    const float* W1   = (const float*)d_in[5];
    const float* b1   = (const float*)d_in[6];
    const float* W2   = (const float*)d_in[7];
    const float* b2   = (const float*)d_in[8];
    const float* W3   = (const float*)d_in[9];
    const float* b3   = (const float*)d_in[10];
    const float* W4   = (const float*)d_in[11];
    const float* b4   = (const float*)d_in[12];
    const float* W5   = (const float*)d_in[13];
    const float* b5   = (const float*)d_in[14];
    float* out = (float*)d_out;

    float *xp, *hs, *bias;
    __nv_bfloat16 *Wbh, *Wbl, *W1h, *W1l;
    cudaGetSymbolAddress((void**)&xp,   g_xp);
    cudaGetSymbolAddress((void**)&hs,   g_hs);
    cudaGetSymbolAddress((void**)&Wbh,  g_Wbh);
    cudaGetSymbolAddress((void**)&Wbl,  g_Wbl);
    cudaGetSymbolAddress((void**)&W1h,  g_W1h);
    cudaGetSymbolAddress((void**)&W1l,  g_W1l);
    cudaGetSymbolAddress((void**)&bias, g_bias);

    cudaFuncSetAttribute(proj_mma_kernel,
                         cudaFuncAttributeMaxDynamicSharedMemorySize, PROJ_SMEM);
    cudaFuncSetAttribute(mlp_kernel,
                         cudaFuncAttributeMaxDynamicSharedMemorySize, MLP_SMEM);

    prep_kernel<<<(HID * KPAD + 255) / 256, 256>>>(W_ih, W1, b_ih, b_hh);
    proj_mma_kernel<<<MROWS / 128, 256, PROJ_SMEM>>>(x, Wbh, Wbl, bias, xp);
    scan_kernel<<<BATCH, 256>>>(xp, W_hh, hs);
    mlp_kernel<<<MROWS / 128, 256, MLP_SMEM>>>(hs, W1h, W1l, b1,
                                               W2, b2, W3, b3, W4, b4, W5, b5, out);
}